// round 10
// baseline (speedup 1.0000x reference)
#include <cuda_runtime.h>
#include <cstdint>
#include <math.h>

#define HID 1024
#define KD  1024
#define NLEAF 8192
#define DEPTH 13

// k-permutation within each 8-float group: [k0,k4,k1,k5,k2,k6,k3,k7]
#define KPERM(k) (((k) & ~7) | (((k) & 3) << 1) | (((k) >> 2) & 1))

// ======================= device scratch =============================================
__device__ float g_h[2][NLEAF * HID];
__device__ float g_c[2][NLEAF * HID];
__device__ float g_hs[(NLEAF / 2) * HID];      // pair-summed child h (tf32, k-permuted)
__device__ float g_g3[(NLEAF / 2) * 3 * HID];
__device__ float g_gf[NLEAF * HID];
__device__ float g_wcat[4 * HID * KD];         // tf32, k-permuted, GATE-INTERLEAVED rows
__device__ float g_ucat3[3 * HID * KD];        // tf32, k-permuted [Ui;Uo;Uu]
__device__ float g_uf[HID * KD];               // tf32, k-permuted Uf
__device__ float g_tok[NLEAF * KD];            // tf32, k-permuted tokens
__device__ float g_opg[4 * 4 * HID];
__device__ float g_lc3[3 * HID];
__device__ float g_lf[2 * HID];

__device__ __forceinline__ float sigf(float x) { return 1.0f / (1.0f + expf(-x)); }

__device__ __forceinline__ uint32_t f2tf(float x) {
    uint32_t r;
    asm("cvt.rna.tf32.f32 %0, %1;" : "=r"(r) : "f"(x));
    return r;
}
__device__ __forceinline__ float f2tf_f(float x) { return __uint_as_float(f2tf(x)); }
__device__ __forceinline__ uint32_t smem_u32(const void* p) {
    uint32_t a;
    asm("{ .reg .u64 t; cvta.to.shared.u64 t, %1; cvt.u32.u64 %0, t; }" : "=r"(a) : "l"(p));
    return a;
}
__device__ __forceinline__ void cp_async16(uint32_t dst, const void* src, int src_bytes) {
    asm volatile("cp.async.cg.shared.global [%0], [%1], 16, %2;"
                 :: "r"(dst), "l"(src), "r"(src_bytes) : "memory");
}

// ======================= precompute (exact fp32, original layouts) ==================
__global__ void precompute_kernel(
    const float* __restrict__ W_i, const float* __restrict__ W_o,
    const float* __restrict__ W_u, const float* __restrict__ W_f,
    const float* __restrict__ U_i, const float* __restrict__ U_o,
    const float* __restrict__ U_u, const float* __restrict__ U_f,
    const float* __restrict__ b_i, const float* __restrict__ b_o,
    const float* __restrict__ b_u, const float* __restrict__ b_f,
    const float* __restrict__ op_emb, const float* __restrict__ h_init)
{
    int t = blockIdx.x * blockDim.x + threadIdx.x;
    if (t < 4 * 4 * HID) {
        int k = t >> 12; int rem = t & 4095; int g = rem >> 10; int hh = rem & 1023;
        const float* W = (g == 0) ? W_i : (g == 1) ? W_o : (g == 2) ? W_u : W_f;
        const float* b = (g == 0) ? b_i : (g == 1) ? b_o : (g == 2) ? b_u : b_f;
        const float* x = op_emb + k * KD;
        const float* w = W + (size_t)hh * KD;
        float acc = b[hh];
        for (int kk = 0; kk < KD; kk++) acc += x[kk] * w[kk];
        g_opg[t] = acc;
    } else if (t < 4 * 4 * HID + 3 * HID) {
        int t2 = t - 4 * 4 * HID; int g = t2 >> 10; int hh = t2 & 1023;
        const float* U = (g == 0) ? U_i : (g == 1) ? U_o : U_u;
        const float* b = (g == 0) ? b_i : (g == 1) ? b_o : b_u;
        const float* u = U + (size_t)hh * KD;
        float acc = b[hh];
        for (int kk = 0; kk < KD; kk++) acc += (h_init[kk] + h_init[KD + kk]) * u[kk];
        g_lc3[t2] = acc;
    } else if (t < 4 * 4 * HID + 3 * HID + 2 * HID) {
        int t2 = t - (4 * 4 * HID + 3 * HID); int ci = t2 >> 10; int hh = t2 & 1023;
        const float* u = U_f + (size_t)hh * KD;
        float acc = b_f[hh];
        for (int kk = 0; kk < KD; kk++) acc += h_init[ci * KD + kk] * u[kk];
        g_lf[t2] = acc;
    }
}

// ===== convert GEMM operands: tf32-round + k-permute; wcat rows gate-interleaved ====
__global__ void conv_tf32_kernel(
    const float* __restrict__ W_i, const float* __restrict__ W_o,
    const float* __restrict__ W_u, const float* __restrict__ W_f,
    const float* __restrict__ U_i, const float* __restrict__ U_o,
    const float* __restrict__ U_u, const float* __restrict__ U_f,
    const float* __restrict__ tokens)
{
    const int SEG = (HID * KD) / 4;                       // 262144 float4
    int idx = blockIdx.x * blockDim.x + threadIdx.x;      // < 16*SEG
    if (idx < 4 * SEG) {
        // Wcat: row (hh of W_g) -> interleaved dst row 4*hh + g
        int s = idx / SEG; size_t off4 = idx % SEG;
        const float4 v = ((const float4*)((s == 0) ? W_i : (s == 1) ? W_o
                                         : (s == 2) ? W_u : W_f))[off4];
        const size_t i = off4 * 4;
        const int hh = (int)(i >> 10);
        const int k  = (int)(i & 1023);
        float* dst = g_wcat + (size_t)(4 * hh + s) * KD + (k & ~7);
        const int o = (k & 4) ? 1 : 0;
        dst[o + 0] = f2tf_f(v.x); dst[o + 2] = f2tf_f(v.y);
        dst[o + 4] = f2tf_f(v.z); dst[o + 6] = f2tf_f(v.w);
        return;
    }
    const float4* src;
    float* dst;
    size_t off4;
    if (idx < 7 * SEG) {
        int s = (idx - 4 * SEG) / SEG; off4 = (idx - 4 * SEG) % SEG;
        src = (const float4*)((s == 0) ? U_i : (s == 1) ? U_o : U_u) + off4;
        dst = g_ucat3 + (size_t)s * (HID * KD);
    } else if (idx < 8 * SEG) {
        off4 = idx - 7 * SEG;
        src = (const float4*)U_f + off4;
        dst = g_uf;
    } else {
        off4 = idx - 8 * SEG;
        src = (const float4*)tokens + off4;
        dst = g_tok;
    }
    float4 v = *src;
    const size_t i = off4 * 4;
    const size_t base = i & ~(size_t)7;
    const int o = (i & 4) ? 1 : 0;
    dst[base + o + 0] = f2tf_f(v.x);
    dst[base + o + 2] = f2tf_f(v.y);
    dst[base + o + 4] = f2tf_f(v.z);
    dst[base + o + 6] = f2tf_f(v.w);
}

// ======================= tf32 mma.sync GEMM core, 256x128 CTA tile ==================
// Operands tf32-rounded + k-permuted. 512 threads, 16 warps (4M x 4N) of 64x32 tiles.
// SMEM: A rows 0..255, B rows 256..383, stride 40 words; 3-stage cp.async.
static constexpr int SMEM_STRIDE = 40;
static constexpr int TOT_ROWS    = 384;
static constexpr int STAGE_WORDS = TOT_ROWS * SMEM_STRIDE;          // 15360
static constexpr int NSTAGE = 3;
static constexpr int GEMM_SMEM_BYTES = NSTAGE * STAGE_WORDS * 4;    // 184320

__device__ __forceinline__ void mma_tf32(float* c, uint32_t a0, uint32_t a1,
                                         uint32_t a2, uint32_t a3,
                                         uint32_t b0, uint32_t b1) {
    asm volatile(
        "mma.sync.aligned.m16n8k8.row.col.f32.tf32.tf32.f32 "
        "{%0,%1,%2,%3}, {%4,%5,%6,%7}, {%8,%9}, {%0,%1,%2,%3};"
        : "+f"(c[0]), "+f"(c[1]), "+f"(c[2]), "+f"(c[3])
        : "r"(a0), "r"(a1), "r"(a2), "r"(a3), "r"(b0), "r"(b1));
}

template <int GATHER>
__device__ __forceinline__ void gemm_mainloop(
    const float* __restrict__ A, const float* __restrict__ B,
    int M, int m0, int n0, const int* __restrict__ ids,
    uint32_t* sm, float acc[4][4][4])
{
    const int tid  = threadIdx.x;
    const int wid  = tid >> 5;
    const int lane = tid & 31;

    // loader: threads 0..255 -> A rows, 256..383 -> B rows, rest idle
    const float* src = nullptr;
    int srcsz = 16;
    const bool ldact = tid < TOT_ROWS;
    if (tid < 256) {
        const int r = m0 + tid;
        const bool ok = r < M;
        const int rr = ok ? (GATHER ? ids[r] : r) : 0;
        src = A + (size_t)rr * KD;
        srcsz = ok ? 16 : 0;
    } else if (tid < TOT_ROWS) {
        src = B + (size_t)(n0 + tid - 256) * KD;
    }
    const uint32_t dbase = smem_u32(sm) + (uint32_t)((ldact ? tid : 0) * SMEM_STRIDE) * 4;

    auto issue = [&](int it) {
        if (ldact) {
            const uint32_t d = dbase + (uint32_t)(it % NSTAGE) * (STAGE_WORDS * 4);
            const float* p = src + it * 32;
            #pragma unroll
            for (int j = 0; j < 8; j++)
                cp_async16(d + j * 16, p + j * 4, srcsz);
        }
        asm volatile("cp.async.commit_group;" ::: "memory");
    };

    const int wm  = (wid & 3) * 64;
    const int wn  = (wid >> 2) * 32;
    const int gid = lane >> 2;
    const int tig = lane & 3;

    #pragma unroll
    for (int mi = 0; mi < 4; mi++)
        #pragma unroll
        for (int ni = 0; ni < 4; ni++)
            #pragma unroll
            for (int e = 0; e < 4; e++) acc[mi][ni][e] = 0.0f;

    auto compute = [&](int s) {
        const uint32_t* st = sm + s * STAGE_WORDS;
        #pragma unroll
        for (int kk = 0; kk < 32; kk += 8) {
            uint2 a[4][2], b[4];
            #pragma unroll
            for (int mi = 0; mi < 4; mi++) {
                const uint32_t* ap = st + (wm + mi * 16 + gid) * SMEM_STRIDE + kk + 2 * tig;
                a[mi][0] = *(const uint2*)ap;
                a[mi][1] = *(const uint2*)(ap + 8 * SMEM_STRIDE);
            }
            #pragma unroll
            for (int ni = 0; ni < 4; ni++)
                b[ni] = *(const uint2*)(st + (256 + wn + ni * 8 + gid) * SMEM_STRIDE
                                        + kk + 2 * tig);
            #pragma unroll
            for (int mi = 0; mi < 4; mi++)
                #pragma unroll
                for (int ni = 0; ni < 4; ni++)
                    mma_tf32(acc[mi][ni],
                             a[mi][0].x, a[mi][1].x, a[mi][0].y, a[mi][1].y,
                             b[ni].x, b[ni].y);
        }
    };

    issue(0);
    issue(1);
    #pragma unroll 1
    for (int it = 0; it < 32; it++) {
        if (it < 31) { asm volatile("cp.async.wait_group 1;" ::: "memory"); }
        else         { asm volatile("cp.async.wait_group 0;" ::: "memory"); }
        __syncthreads();
        if (it + 2 < 32) issue(it + 2);
        compute(it % NSTAGE);
    }
}

// ---- leaf GEMM with FUSED gate epilogue (Wcat gate-interleaved: col n = 4*hh+g) ----
__global__ void __launch_bounds__(512, 1)
leaf_gemm_fused(const float* __restrict__ A, const float* __restrict__ B,
                const int* __restrict__ ids, const float* __restrict__ c_init,
                float* __restrict__ c_out, float* __restrict__ h_out,
                float* __restrict__ hs_out)
{
    extern __shared__ __align__(16) uint32_t sm[];
    const int m0 = blockIdx.y * 256;
    const int n0 = blockIdx.x * 128;
    float acc[4][4][4];
    gemm_mainloop<1>(A, B, NLEAF, m0, n0, ids, sm, acc);

    const int wid  = threadIdx.x >> 5;
    const int lane = threadIdx.x & 31;
    const int wm  = (wid & 3) * 64;
    const int wn  = (wid >> 2) * 32;
    const int gid = lane >> 2;
    const int tig = lane & 3;
    const int pbit = tig & 1;           // 0: holds (i,o) preacts; 1: holds (u,f)

    #pragma unroll
    for (int ni = 0; ni < 4; ni++) {
        const int hh = ((n0 + wn) >> 2) + ni * 2 + (tig >> 1);
        const int hp = KPERM(hh);
        const float lci = g_lc3[hh], lco = g_lc3[HID + hh], lcu = g_lc3[2 * HID + hh];
        const float lf0 = g_lf[hh],  lf1 = g_lf[HID + hh];
        const float ci0 = c_init[hh], ci1 = c_init[HID + hh];
        #pragma unroll
        for (int mi = 0; mi < 4; mi++) {
            #pragma unroll
            for (int half = 0; half < 2; half++) {
                const int r = m0 + wm + mi * 16 + gid + half * 8;
                const float x0 = acc[mi][ni][half * 2 + 0];
                const float x1 = acc[mi][ni][half * 2 + 1];
                const float p0 = __shfl_xor_sync(0xFFFFFFFFu, x0, 1);
                const float p1 = __shfl_xor_sync(0xFFFFFFFFu, x1, 1);
                // even lane: (x0,x1)=(xi,xo), (p0,p1)=(xu,xf)
                const float gi = sigf(x0 + lci);
                const float go = sigf(x1 + lco);
                const float gu = tanhf(p0 + lcu);
                const float xf = p1;
                const float c = gi * gu + sigf(xf + lf0) * ci0 + sigf(xf + lf1) * ci1;
                const float h = go * tanhf(c);
                const float hsib = __shfl_xor_sync(0xFFFFFFFFu, h, 4);  // sibling leaf
                if (pbit == 0) {
                    c_out[(size_t)r * HID + hh] = c;
                    h_out[(size_t)r * HID + hp] = f2tf_f(h);
                    if ((gid & 1) == 0)
                        hs_out[(size_t)(r >> 1) * HID + hp] = f2tf_f(h + hsib);
                }
            }
        }
    }
}

// ---- merged per-level GEMM: bx<24 -> G3 (hs@U3^T), bx>=24 -> Gf (h@Uf^T) -----------
__global__ void __launch_bounds__(512, 1)
level_gemm(const float* __restrict__ hs, const float* __restrict__ h,
           const float* __restrict__ U3, const float* __restrict__ Uf,
           float* __restrict__ g3, float* __restrict__ gf, int m)
{
    extern __shared__ __align__(16) uint32_t sm[];
    const int bx = blockIdx.x;
    const int m0 = blockIdx.y * 256;
    const float* A;
    const float* B;
    float* C;
    int M, N, n0;
    if (bx < 24) {
        if (m0 >= m) return;
        A = hs; B = U3; C = g3; M = m; N = 3 * HID; n0 = bx * 128;
    } else {
        if (m0 >= 2 * m) return;
        A = h; B = Uf; C = gf; M = 2 * m; N = HID; n0 = (bx - 24) * 128;
    }
    float acc[4][4][4];
    gemm_mainloop<0>(A, B, M, m0, n0, nullptr, sm, acc);

    const int wid  = threadIdx.x >> 5;
    const int lane = threadIdx.x & 31;
    const int wm  = (wid & 3) * 64;
    const int wn  = (wid >> 2) * 32;
    const int gid = lane >> 2;
    const int tig = lane & 3;
    #pragma unroll
    for (int mi = 0; mi < 4; mi++) {
        const int r0 = m0 + wm + mi * 16 + gid;
        #pragma unroll
        for (int ni = 0; ni < 4; ni++) {
            const int col = n0 + wn + ni * 8 + tig * 2;
            if (r0 < M)
                *(float2*)(C + (size_t)r0 * N + col) = make_float2(acc[mi][ni][0], acc[mi][ni][1]);
            if (r0 + 8 < M)
                *(float2*)(C + (size_t)(r0 + 8) * N + col) = make_float2(acc[mi][ni][2], acc[mi][ni][3]);
        }
    }
}

// ========== node gate epilogues (pair-fused; h & hs tf32-rounded, k-permuted) =======
__global__ void node_gate_pair_kernel(int m, int off, const int* __restrict__ op_ids,
                                      const float* __restrict__ c_in,
                                      float* __restrict__ c_out, float* __restrict__ h_out,
                                      float* __restrict__ hs_out)
{
    int idx = blockIdx.x * blockDim.x + threadIdx.x;
    if (idx >= (m >> 1) * HID) return;
    int hh = idx & 1023;
    int p = idx >> 10;
    const int hp = KPERM(hh);
    float hsum = 0.0f;
    #pragma unroll
    for (int s = 0; s < 2; s++) {
        const int j = 2 * p + s;
        const float* og = g_opg + op_ids[off + j] * 4 * HID;
        const float* g3 = g_g3 + (size_t)j * 3 * HID;
        float i = sigf(og[hh]            + g3[hh]);
        float o = sigf(og[HID + hh]      + g3[HID + hh]);
        float u = tanhf(og[2 * HID + hh] + g3[2 * HID + hh]);
        float xf = og[3 * HID + hh];
        float f0 = sigf(xf + g_gf[(size_t)(2 * j) * HID + hh]);
        float f1 = sigf(xf + g_gf[(size_t)(2 * j + 1) * HID + hh]);
        float c = i * u + f0 * c_in[(size_t)(2 * j) * HID + hh]
                        + f1 * c_in[(size_t)(2 * j + 1) * HID + hh];
        float h = o * tanhf(c);
        c_out[(size_t)j * HID + hh] = c;
        h_out[(size_t)j * HID + hp] = f2tf_f(h);
        hsum += h;
    }
    hs_out[(size_t)p * HID + hp] = f2tf_f(hsum);
}

__global__ void node_gate_root_kernel(const int* __restrict__ op_ids,
                                      const float* __restrict__ c_in,
                                      float* __restrict__ c_out, float* __restrict__ h_out)
{
    int hh = blockIdx.x * blockDim.x + threadIdx.x;
    if (hh >= HID) return;
    const float* og = g_opg + op_ids[0] * 4 * HID;
    float i = sigf(og[hh]            + g_g3[hh]);
    float o = sigf(og[HID + hh]      + g_g3[HID + hh]);
    float u = tanhf(og[2 * HID + hh] + g_g3[2 * HID + hh]);
    float xf = og[3 * HID + hh];
    float f0 = sigf(xf + g_gf[hh]);
    float f1 = sigf(xf + g_gf[HID + hh]);
    float c = i * u + f0 * c_in[hh] + f1 * c_in[HID + hh];
    c_out[hh] = c;
    h_out[hh] = o * tanhf(c);
}

// ======================= host launch ================================================
extern "C" void kernel_launch(void* const* d_in, const int* in_sizes, int n_in,
                              void* d_out, int out_size)
{
    const float* tokens   = (const float*)d_in[0];
    const int*   leaf_ids = (const int*)  d_in[1];
    const int*   op_ids   = (const int*)  d_in[2];
    const float* W_i = (const float*)d_in[3];
    const float* W_o = (const float*)d_in[4];
    const float* W_u = (const float*)d_in[5];
    const float* W_f = (const float*)d_in[6];
    const float* U_i = (const float*)d_in[7];
    const float* U_o = (const float*)d_in[8];
    const float* U_u = (const float*)d_in[9];
    const float* U_f = (const float*)d_in[10];
    const float* b_i = (const float*)d_in[11];
    const float* b_o = (const float*)d_in[12];
    const float* b_u = (const float*)d_in[13];
    const float* b_f = (const float*)d_in[14];
    const float* op_emb = (const float*)d_in[15];
    const float* c_init = (const float*)d_in[16];
    const float* h_init = (const float*)d_in[17];
    float* out = (float*)d_out;

    cudaFuncSetAttribute(leaf_gemm_fused, cudaFuncAttributeMaxDynamicSharedMemorySize, GEMM_SMEM_BYTES);
    cudaFuncSetAttribute(level_gemm,      cudaFuncAttributeMaxDynamicSharedMemorySize, GEMM_SMEM_BYTES);

    void* p;
    cudaGetSymbolAddress(&p, g_h);     float* hbase = (float*)p;
    cudaGetSymbolAddress(&p, g_c);     float* cbase = (float*)p;
    cudaGetSymbolAddress(&p, g_hs);    float* hsp   = (float*)p;
    cudaGetSymbolAddress(&p, g_g3);    float* g3p   = (float*)p;
    cudaGetSymbolAddress(&p, g_gf);    float* gfp   = (float*)p;
    cudaGetSymbolAddress(&p, g_wcat);  float* wcat  = (float*)p;
    cudaGetSymbolAddress(&p, g_ucat3); float* ucat3 = (float*)p;
    cudaGetSymbolAddress(&p, g_uf);    float* ufp   = (float*)p;
    cudaGetSymbolAddress(&p, g_tok);   float* tokp  = (float*)p;

    float* hbuf[2] = { hbase, hbase + (size_t)NLEAF * HID };
    float* cbuf[2] = { cbase, cbase + (size_t)NLEAF * HID };

    conv_tf32_kernel<<<(16 * (HID * KD / 4)) / 256, 256>>>(
        W_i, W_o, W_u, W_f, U_i, U_o, U_u, U_f, tokens);
    precompute_kernel<<<84, 256>>>(W_i, W_o, W_u, W_f, U_i, U_o, U_u, U_f,
                                   b_i, b_o, b_u, b_f, op_emb, h_init);

    // Leaf level: GEMM + gates fused (M=8192, N=4096 gate-interleaved)
    leaf_gemm_fused<<<dim3(4 * HID / 128, NLEAF / 256), 512, GEMM_SMEM_BYTES>>>(
        tokp, wcat, leaf_ids, c_init, cbuf[0], hbuf[0], hsp);

    int cur = 0;
    for (int l = DEPTH - 1; l >= 0; l--) {
        const int m = 1 << l;
        const int off = m - 1;
        const int nxt = cur ^ 1;
        level_gemm<<<dim3(32, (2 * m + 255) / 256), 512, GEMM_SMEM_BYTES>>>(
            hsp, hbuf[cur], ucat3, ufp, g3p, gfp, m);
        if (m > 1) {
            node_gate_pair_kernel<<<((m / 2) * HID + 255) / 256, 256>>>(
                m, off, op_ids, cbuf[cur], cbuf[nxt], hbuf[nxt], hsp);
        } else {
            node_gate_root_kernel<<<4, 256>>>(op_ids, cbuf[cur], cbuf[nxt], hbuf[nxt]);
        }
        cur = nxt;
    }

    cudaMemcpyAsync(out,       cbuf[cur], HID * sizeof(float), cudaMemcpyDeviceToDevice, 0);
    cudaMemcpyAsync(out + HID, hbuf[cur], HID * sizeof(float), cudaMemcpyDeviceToDevice, 0);
}

// round 11
// speedup vs baseline: 1.0383x; 1.0383x over previous
#include <cuda_runtime.h>
#include <cstdint>
#include <math.h>

#define HID 1024
#define KD  1024
#define NLEAF 8192
#define DEPTH 13

// k-permutation within each 8-float group: [k0,k4,k1,k5,k2,k6,k3,k7]
#define KPERM(k) (((k) & ~7) | (((k) & 3) << 1) | (((k) >> 2) & 1))

// ======================= device scratch =============================================
__device__ float g_h[2][NLEAF * HID];
__device__ float g_c[2][NLEAF * HID];
__device__ float g_hs[(NLEAF / 2) * HID];      // pair-summed child h (tf32, k-permuted)
__device__ float g_g3[(NLEAF / 2) * 3 * HID];
__device__ float g_gf[NLEAF * HID];
__device__ float g_wcat[4 * HID * KD];         // tf32, k-permuted, GATE-INTERLEAVED rows
__device__ float g_ucat3[3 * HID * KD];        // tf32, k-permuted [Ui;Uo;Uu]
__device__ float g_uf[HID * KD];               // tf32, k-permuted Uf
__device__ float g_tok[NLEAF * KD];            // tf32, k-permuted tokens
__device__ float g_opg[4 * 4 * HID];
__device__ float g_lc3[3 * HID];
__device__ float g_lf[2 * HID];

__device__ __forceinline__ float sigf(float x) { return 1.0f / (1.0f + expf(-x)); }

__device__ __forceinline__ uint32_t f2tf(float x) {
    uint32_t r;
    asm("cvt.rna.tf32.f32 %0, %1;" : "=r"(r) : "f"(x));
    return r;
}
__device__ __forceinline__ float f2tf_f(float x) { return __uint_as_float(f2tf(x)); }
__device__ __forceinline__ uint32_t smem_u32(const void* p) {
    uint32_t a;
    asm("{ .reg .u64 t; cvta.to.shared.u64 t, %1; cvt.u32.u64 %0, t; }" : "=r"(a) : "l"(p));
    return a;
}
__device__ __forceinline__ void cp_async16(uint32_t dst, const void* src, int src_bytes) {
    asm volatile("cp.async.cg.shared.global [%0], [%1], 16, %2;"
                 :: "r"(dst), "l"(src), "r"(src_bytes) : "memory");
}

// ======================= precompute (exact fp32, original layouts) ==================
__global__ void precompute_kernel(
    const float* __restrict__ W_i, const float* __restrict__ W_o,
    const float* __restrict__ W_u, const float* __restrict__ W_f,
    const float* __restrict__ U_i, const float* __restrict__ U_o,
    const float* __restrict__ U_u, const float* __restrict__ U_f,
    const float* __restrict__ b_i, const float* __restrict__ b_o,
    const float* __restrict__ b_u, const float* __restrict__ b_f,
    const float* __restrict__ op_emb, const float* __restrict__ h_init)
{
    int t = blockIdx.x * blockDim.x + threadIdx.x;
    if (t < 4 * 4 * HID) {
        int k = t >> 12; int rem = t & 4095; int g = rem >> 10; int hh = rem & 1023;
        const float* W = (g == 0) ? W_i : (g == 1) ? W_o : (g == 2) ? W_u : W_f;
        const float* b = (g == 0) ? b_i : (g == 1) ? b_o : (g == 2) ? b_u : b_f;
        const float* x = op_emb + k * KD;
        const float* w = W + (size_t)hh * KD;
        float acc = b[hh];
        for (int kk = 0; kk < KD; kk++) acc += x[kk] * w[kk];
        g_opg[t] = acc;
    } else if (t < 4 * 4 * HID + 3 * HID) {
        int t2 = t - 4 * 4 * HID; int g = t2 >> 10; int hh = t2 & 1023;
        const float* U = (g == 0) ? U_i : (g == 1) ? U_o : U_u;
        const float* b = (g == 0) ? b_i : (g == 1) ? b_o : b_u;
        const float* u = U + (size_t)hh * KD;
        float acc = b[hh];
        for (int kk = 0; kk < KD; kk++) acc += (h_init[kk] + h_init[KD + kk]) * u[kk];
        g_lc3[t2] = acc;
    } else if (t < 4 * 4 * HID + 3 * HID + 2 * HID) {
        int t2 = t - (4 * 4 * HID + 3 * HID); int ci = t2 >> 10; int hh = t2 & 1023;
        const float* u = U_f + (size_t)hh * KD;
        float acc = b_f[hh];
        for (int kk = 0; kk < KD; kk++) acc += h_init[ci * KD + kk] * u[kk];
        g_lf[t2] = acc;
    }
}

// ===== convert GEMM operands: tf32-round + k-permute; wcat rows gate-interleaved ====
__global__ void conv_tf32_kernel(
    const float* __restrict__ W_i, const float* __restrict__ W_o,
    const float* __restrict__ W_u, const float* __restrict__ W_f,
    const float* __restrict__ U_i, const float* __restrict__ U_o,
    const float* __restrict__ U_u, const float* __restrict__ U_f,
    const float* __restrict__ tokens)
{
    const int SEG = (HID * KD) / 4;                       // 262144 float4
    int idx = blockIdx.x * blockDim.x + threadIdx.x;      // < 16*SEG
    if (idx < 4 * SEG) {
        // Wcat: row (hh of W_g) -> interleaved dst row 4*hh + g
        int s = idx / SEG; size_t off4 = idx % SEG;
        const float4 v = ((const float4*)((s == 0) ? W_i : (s == 1) ? W_o
                                         : (s == 2) ? W_u : W_f))[off4];
        const size_t i = off4 * 4;
        const int hh = (int)(i >> 10);
        const int k  = (int)(i & 1023);
        float* dst = g_wcat + (size_t)(4 * hh + s) * KD + (k & ~7);
        const int o = (k & 4) ? 1 : 0;
        dst[o + 0] = f2tf_f(v.x); dst[o + 2] = f2tf_f(v.y);
        dst[o + 4] = f2tf_f(v.z); dst[o + 6] = f2tf_f(v.w);
        return;
    }
    const float4* src;
    float* dst;
    size_t off4;
    if (idx < 7 * SEG) {
        int s = (idx - 4 * SEG) / SEG; off4 = (idx - 4 * SEG) % SEG;
        src = (const float4*)((s == 0) ? U_i : (s == 1) ? U_o : U_u) + off4;
        dst = g_ucat3 + (size_t)s * (HID * KD);
    } else if (idx < 8 * SEG) {
        off4 = idx - 7 * SEG;
        src = (const float4*)U_f + off4;
        dst = g_uf;
    } else {
        off4 = idx - 8 * SEG;
        src = (const float4*)tokens + off4;
        dst = g_tok;
    }
    float4 v = *src;
    const size_t i = off4 * 4;
    const size_t base = i & ~(size_t)7;
    const int o = (i & 4) ? 1 : 0;
    dst[base + o + 0] = f2tf_f(v.x);
    dst[base + o + 2] = f2tf_f(v.y);
    dst[base + o + 4] = f2tf_f(v.z);
    dst[base + o + 6] = f2tf_f(v.w);
}

// ======================= tf32 mma.sync GEMM core, 128x128 CTA tile ==================
// Operands tf32-rounded + k-permuted. 512 threads, 16 warps (4M x 4N) of 32x32 tiles.
// SMEM: A rows 0..127, B rows 128..255, stride 40 words; 3-stage cp.async.
static constexpr int SMEM_STRIDE = 40;
static constexpr int STAGE_WORDS = 256 * SMEM_STRIDE;              // 10240 words
static constexpr int NSTAGE = 3;
static constexpr int GEMM_SMEM_BYTES = NSTAGE * STAGE_WORDS * 4;   // 122880

__device__ __forceinline__ void mma_tf32(float* c, uint32_t a0, uint32_t a1,
                                         uint32_t a2, uint32_t a3,
                                         uint32_t b0, uint32_t b1) {
    asm volatile(
        "mma.sync.aligned.m16n8k8.row.col.f32.tf32.tf32.f32 "
        "{%0,%1,%2,%3}, {%4,%5,%6,%7}, {%8,%9}, {%0,%1,%2,%3};"
        : "+f"(c[0]), "+f"(c[1]), "+f"(c[2]), "+f"(c[3])
        : "r"(a0), "r"(a1), "r"(a2), "r"(a3), "r"(b0), "r"(b1));
}

template <int GATHER>
__device__ __forceinline__ void gemm_mainloop(
    const float* __restrict__ A, const float* __restrict__ B,
    int M, int m0, int n0, const int* __restrict__ ids,
    uint32_t* sm, float acc[2][4][4])
{
    const int tid  = threadIdx.x;
    const int wid  = tid >> 5;
    const int lane = tid & 31;

    // ---- loader: 2 threads/row (256 rows: 0-127 A, 128-255 B), 16 floats each ----
    const int lrow = tid >> 1;
    const int fcol = (tid & 1) * 16;
    const float* src;
    int srcsz = 16;
    if (lrow < 128) {
        const int r = m0 + lrow;
        const bool ok = r < M;
        const int rr = ok ? (GATHER ? ids[r] : r) : 0;
        src = A + (size_t)rr * KD + fcol;
        srcsz = ok ? 16 : 0;
    } else {
        src = B + (size_t)(n0 + lrow - 128) * KD + fcol;
    }
    const uint32_t dbase = smem_u32(sm) + (uint32_t)(lrow * SMEM_STRIDE + fcol) * 4;

    auto issue = [&](int it) {
        const uint32_t d = dbase + (uint32_t)(it % NSTAGE) * (STAGE_WORDS * 4);
        const float* p = src + it * 32;
        #pragma unroll
        for (int j = 0; j < 4; j++)
            cp_async16(d + j * 16, p + j * 4, srcsz);
        asm volatile("cp.async.commit_group;" ::: "memory");
    };

    // ---- 16 warps: 4 along M x 4 along N, 32x32 warptiles ----
    const int wm  = (wid & 3) * 32;
    const int wn  = (wid >> 2) * 32;
    const int gid = lane >> 2;
    const int tig = lane & 3;

    #pragma unroll
    for (int mi = 0; mi < 2; mi++)
        #pragma unroll
        for (int ni = 0; ni < 4; ni++)
            #pragma unroll
            for (int e = 0; e < 4; e++) acc[mi][ni][e] = 0.0f;

    auto compute = [&](int s) {
        const uint32_t* st = sm + s * STAGE_WORDS;
        #pragma unroll
        for (int kk = 0; kk < 32; kk += 8) {
            // permuted layout: (k=tig, k=tig+4) adjacent at word offset kk + 2*tig
            uint2 a[2][2], b[4];
            #pragma unroll
            for (int mi = 0; mi < 2; mi++) {
                const uint32_t* ap = st + (wm + mi * 16 + gid) * SMEM_STRIDE + kk + 2 * tig;
                a[mi][0] = *(const uint2*)ap;
                a[mi][1] = *(const uint2*)(ap + 8 * SMEM_STRIDE);
            }
            #pragma unroll
            for (int ni = 0; ni < 4; ni++)
                b[ni] = *(const uint2*)(st + (128 + wn + ni * 8 + gid) * SMEM_STRIDE
                                        + kk + 2 * tig);
            #pragma unroll
            for (int mi = 0; mi < 2; mi++)
                #pragma unroll
                for (int ni = 0; ni < 4; ni++)
                    mma_tf32(acc[mi][ni],
                             a[mi][0].x, a[mi][1].x, a[mi][0].y, a[mi][1].y,
                             b[ni].x, b[ni].y);
        }
    };

    issue(0);
    issue(1);
    #pragma unroll 1
    for (int it = 0; it < 32; it++) {
        if (it < 31) { asm volatile("cp.async.wait_group 1;" ::: "memory"); }
        else         { asm volatile("cp.async.wait_group 0;" ::: "memory"); }
        __syncthreads();
        if (it + 2 < 32) issue(it + 2);
        compute(it % NSTAGE);
    }
}

// ---- leaf GEMM with FUSED gate epilogue (Wcat gate-interleaved: col n = 4*hh+g) ----
__global__ void __launch_bounds__(512, 1)
leaf_gemm_fused(const float* __restrict__ A, const float* __restrict__ B,
                const int* __restrict__ ids, const float* __restrict__ c_init,
                float* __restrict__ c_out, float* __restrict__ h_out,
                float* __restrict__ hs_out)
{
    extern __shared__ __align__(16) uint32_t sm[];
    const int m0 = blockIdx.y * 128;
    const int n0 = blockIdx.x * 128;
    float acc[2][4][4];
    gemm_mainloop<1>(A, B, NLEAF, m0, n0, ids, sm, acc);

    const int wid  = threadIdx.x >> 5;
    const int lane = threadIdx.x & 31;
    const int wm  = (wid & 3) * 32;
    const int wn  = (wid >> 2) * 32;
    const int gid = lane >> 2;
    const int tig = lane & 3;
    const int pbit = tig & 1;           // 0: holds (i,o) preacts; 1: holds (u,f)

    #pragma unroll
    for (int ni = 0; ni < 4; ni++) {
        const int hh = ((n0 + wn) >> 2) + ni * 2 + (tig >> 1);
        const int hp = KPERM(hh);
        const float lci = g_lc3[hh], lco = g_lc3[HID + hh], lcu = g_lc3[2 * HID + hh];
        const float lf0 = g_lf[hh],  lf1 = g_lf[HID + hh];
        const float ci0 = c_init[hh], ci1 = c_init[HID + hh];
        #pragma unroll
        for (int mi = 0; mi < 2; mi++) {
            #pragma unroll
            for (int half = 0; half < 2; half++) {
                const int r = m0 + wm + mi * 16 + gid + half * 8;
                const float x0 = acc[mi][ni][half * 2 + 0];
                const float x1 = acc[mi][ni][half * 2 + 1];
                const float p0 = __shfl_xor_sync(0xFFFFFFFFu, x0, 1);
                const float p1 = __shfl_xor_sync(0xFFFFFFFFu, x1, 1);
                // even lane: (x0,x1)=(xi,xo), (p0,p1)=(xu,xf)
                const float gi = sigf(x0 + lci);
                const float go = sigf(x1 + lco);
                const float gu = tanhf(p0 + lcu);
                const float xf = p1;
                const float c = gi * gu + sigf(xf + lf0) * ci0 + sigf(xf + lf1) * ci1;
                const float h = go * tanhf(c);
                const float hsib = __shfl_xor_sync(0xFFFFFFFFu, h, 4);  // sibling leaf
                if (pbit == 0) {
                    c_out[(size_t)r * HID + hh] = c;
                    h_out[(size_t)r * HID + hp] = f2tf_f(h);
                    if ((gid & 1) == 0)
                        hs_out[(size_t)(r >> 1) * HID + hp] = f2tf_f(h + hsib);
                }
            }
        }
    }
}

// ---- merged per-level GEMM: bx<24 -> G3 (hs@U3^T), bx>=24 -> Gf (h@Uf^T) -----------
__global__ void __launch_bounds__(512, 1)
level_gemm(const float* __restrict__ hs, const float* __restrict__ h,
           const float* __restrict__ U3, const float* __restrict__ Uf,
           float* __restrict__ g3, float* __restrict__ gf, int m)
{
    extern __shared__ __align__(16) uint32_t sm[];
    const int bx = blockIdx.x;
    const int m0 = blockIdx.y * 128;
    const float* A;
    const float* B;
    float* C;
    int M, N, n0;
    if (bx < 24) {
        if (m0 >= m) return;
        A = hs; B = U3; C = g3; M = m; N = 3 * HID; n0 = bx * 128;
    } else {
        if (m0 >= 2 * m) return;
        A = h; B = Uf; C = gf; M = 2 * m; N = HID; n0 = (bx - 24) * 128;
    }
    float acc[2][4][4];
    gemm_mainloop<0>(A, B, M, m0, n0, nullptr, sm, acc);

    const int wid  = threadIdx.x >> 5;
    const int lane = threadIdx.x & 31;
    const int wm  = (wid & 3) * 32;
    const int wn  = (wid >> 2) * 32;
    const int gid = lane >> 2;
    const int tig = lane & 3;
    #pragma unroll
    for (int mi = 0; mi < 2; mi++) {
        const int r0 = m0 + wm + mi * 16 + gid;
        #pragma unroll
        for (int ni = 0; ni < 4; ni++) {
            const int col = n0 + wn + ni * 8 + tig * 2;
            if (r0 < M)
                *(float2*)(C + (size_t)r0 * N + col) = make_float2(acc[mi][ni][0], acc[mi][ni][1]);
            if (r0 + 8 < M)
                *(float2*)(C + (size_t)(r0 + 8) * N + col) = make_float2(acc[mi][ni][2], acc[mi][ni][3]);
        }
    }
}

// ========== node gate epilogues (pair-fused; h & hs tf32-rounded, k-permuted) =======
__global__ void node_gate_pair_kernel(int m, int off, const int* __restrict__ op_ids,
                                      const float* __restrict__ c_in,
                                      float* __restrict__ c_out, float* __restrict__ h_out,
                                      float* __restrict__ hs_out)
{
    int idx = blockIdx.x * blockDim.x + threadIdx.x;
    if (idx >= (m >> 1) * HID) return;
    int hh = idx & 1023;
    int p = idx >> 10;
    const int hp = KPERM(hh);
    float hsum = 0.0f;
    #pragma unroll
    for (int s = 0; s < 2; s++) {
        const int j = 2 * p + s;
        const float* og = g_opg + op_ids[off + j] * 4 * HID;
        const float* g3 = g_g3 + (size_t)j * 3 * HID;
        float i = sigf(og[hh]            + g3[hh]);
        float o = sigf(og[HID + hh]      + g3[HID + hh]);
        float u = tanhf(og[2 * HID + hh] + g3[2 * HID + hh]);
        float xf = og[3 * HID + hh];
        float f0 = sigf(xf + g_gf[(size_t)(2 * j) * HID + hh]);
        float f1 = sigf(xf + g_gf[(size_t)(2 * j + 1) * HID + hh]);
        float c = i * u + f0 * c_in[(size_t)(2 * j) * HID + hh]
                        + f1 * c_in[(size_t)(2 * j + 1) * HID + hh];
        float h = o * tanhf(c);
        c_out[(size_t)j * HID + hh] = c;
        h_out[(size_t)j * HID + hp] = f2tf_f(h);
        hsum += h;
    }
    hs_out[(size_t)p * HID + hp] = f2tf_f(hsum);
}

__global__ void node_gate_root_kernel(const int* __restrict__ op_ids,
                                      const float* __restrict__ c_in,
                                      float* __restrict__ c_out, float* __restrict__ h_out)
{
    int hh = blockIdx.x * blockDim.x + threadIdx.x;
    if (hh >= HID) return;
    const float* og = g_opg + op_ids[0] * 4 * HID;
    float i = sigf(og[hh]            + g_g3[hh]);
    float o = sigf(og[HID + hh]      + g_g3[HID + hh]);
    float u = tanhf(og[2 * HID + hh] + g_g3[2 * HID + hh]);
    float xf = og[3 * HID + hh];
    float f0 = sigf(xf + g_gf[hh]);
    float f1 = sigf(xf + g_gf[HID + hh]);
    float c = i * u + f0 * c_in[hh] + f1 * c_in[HID + hh];
    c_out[hh] = c;
    h_out[hh] = o * tanhf(c);
}

// ======================= host launch ================================================
extern "C" void kernel_launch(void* const* d_in, const int* in_sizes, int n_in,
                              void* d_out, int out_size)
{
    const float* tokens   = (const float*)d_in[0];
    const int*   leaf_ids = (const int*)  d_in[1];
    const int*   op_ids   = (const int*)  d_in[2];
    const float* W_i = (const float*)d_in[3];
    const float* W_o = (const float*)d_in[4];
    const float* W_u = (const float*)d_in[5];
    const float* W_f = (const float*)d_in[6];
    const float* U_i = (const float*)d_in[7];
    const float* U_o = (const float*)d_in[8];
    const float* U_u = (const float*)d_in[9];
    const float* U_f = (const float*)d_in[10];
    const float* b_i = (const float*)d_in[11];
    const float* b_o = (const float*)d_in[12];
    const float* b_u = (const float*)d_in[13];
    const float* b_f = (const float*)d_in[14];
    const float* op_emb = (const float*)d_in[15];
    const float* c_init = (const float*)d_in[16];
    const float* h_init = (const float*)d_in[17];
    float* out = (float*)d_out;

    cudaFuncSetAttribute(leaf_gemm_fused, cudaFuncAttributeMaxDynamicSharedMemorySize, GEMM_SMEM_BYTES);
    cudaFuncSetAttribute(level_gemm,      cudaFuncAttributeMaxDynamicSharedMemorySize, GEMM_SMEM_BYTES);

    void* p;
    cudaGetSymbolAddress(&p, g_h);     float* hbase = (float*)p;
    cudaGetSymbolAddress(&p, g_c);     float* cbase = (float*)p;
    cudaGetSymbolAddress(&p, g_hs);    float* hsp   = (float*)p;
    cudaGetSymbolAddress(&p, g_g3);    float* g3p   = (float*)p;
    cudaGetSymbolAddress(&p, g_gf);    float* gfp   = (float*)p;
    cudaGetSymbolAddress(&p, g_wcat);  float* wcat  = (float*)p;
    cudaGetSymbolAddress(&p, g_ucat3); float* ucat3 = (float*)p;
    cudaGetSymbolAddress(&p, g_uf);    float* ufp   = (float*)p;
    cudaGetSymbolAddress(&p, g_tok);   float* tokp  = (float*)p;

    float* hbuf[2] = { hbase, hbase + (size_t)NLEAF * HID };
    float* cbuf[2] = { cbase, cbase + (size_t)NLEAF * HID };

    conv_tf32_kernel<<<(16 * (HID * KD / 4)) / 256, 256>>>(
        W_i, W_o, W_u, W_f, U_i, U_o, U_u, U_f, tokens);
    precompute_kernel<<<84, 256>>>(W_i, W_o, W_u, W_f, U_i, U_o, U_u, U_f,
                                   b_i, b_o, b_u, b_f, op_emb, h_init);

    // Leaf level: GEMM + gates fused (M=8192, N=4096 gate-interleaved)
    leaf_gemm_fused<<<dim3(4 * HID / 128, NLEAF / 128), 512, GEMM_SMEM_BYTES>>>(
        tokp, wcat, leaf_ids, c_init, cbuf[0], hbuf[0], hsp);

    int cur = 0;
    for (int l = DEPTH - 1; l >= 0; l--) {
        const int m = 1 << l;
        const int off = m - 1;
        const int nxt = cur ^ 1;
        level_gemm<<<dim3(32, (2 * m + 127) / 128), 512, GEMM_SMEM_BYTES>>>(
            hsp, hbuf[cur], ucat3, ufp, g3p, gfp, m);
        if (m > 1) {
            node_gate_pair_kernel<<<((m / 2) * HID + 255) / 256, 256>>>(
                m, off, op_ids, cbuf[cur], cbuf[nxt], hbuf[nxt], hsp);
        } else {
            node_gate_root_kernel<<<4, 256>>>(op_ids, cbuf[cur], cbuf[nxt], hbuf[nxt]);
        }
        cur = nxt;
    }

    cudaMemcpyAsync(out,       cbuf[cur], HID * sizeof(float), cudaMemcpyDeviceToDevice, 0);
    cudaMemcpyAsync(out + HID, hbuf[cur], HID * sizeof(float), cudaMemcpyDeviceToDevice, 0);
}

// round 15
// speedup vs baseline: 1.6683x; 1.6067x over previous
#include <cuda_runtime.h>
#include <cstdint>
#include <math.h>

#define HID 1024
#define KD  1024
#define NLEAF 8192
#define DEPTH 13

// k-permutation within each 8-float group: [k0,k4,k1,k5,k2,k6,k3,k7]
#define KPERM(k) (((k) & ~7) | (((k) & 3) << 1) | (((k) >> 2) & 1))

// Chunk-tiled GEMM operand layout: [r>>7][k>>5][r&127][32 floats], where the
// 32 floats are k-permuted and XOR-swizzled (u2 index ^ ((r&3)<<2)) so that a
// linear 16KB bulk copy into smem yields conflict-free LDS.64 fragment loads.
__device__ __forceinline__ size_t tiled_off(int r, int k) {
    const int w = KPERM(k) & 31;
    const int physw = ((((w >> 1) ^ ((r & 3) << 2)) & 15) << 1) | (w & 1);
    return ((size_t)(r >> 7) * 32 + (k >> 5)) * 4096 + (size_t)((r & 127) * 32 + physw);
}

// ======================= device scratch =============================================
__device__ float g_h[2][NLEAF * HID];          // tiled layout (rows = nodes)
__device__ float g_c[2][NLEAF * HID];          // natural layout
__device__ float g_hs[(NLEAF / 2) * HID];      // tiled layout (rows = pairs)
__device__ float g_g3[(NLEAF / 2) * 3 * HID];  // natural
__device__ float g_gf[NLEAF * HID];            // natural
__device__ float g_wcat[4 * HID * KD];         // tiled, gate-interleaved rows 4*hh+g
__device__ float g_ucat3[3 * HID * KD];        // tiled
__device__ float g_uf[HID * KD];               // tiled
__device__ float g_tok[NLEAF * KD];            // tiled, PRE-GATHERED by leaf_ids
__device__ float g_opg[4 * 4 * HID];
__device__ float g_lc3[3 * HID];
__device__ float g_lf[2 * HID];

__device__ __forceinline__ float sigf(float x) { return 1.0f / (1.0f + expf(-x)); }

__device__ __forceinline__ uint32_t f2tf(float x) {
    uint32_t r;
    asm("cvt.rna.tf32.f32 %0, %1;" : "=r"(r) : "f"(x));
    return r;
}
__device__ __forceinline__ float f2tf_f(float x) { return __uint_as_float(f2tf(x)); }
__device__ __forceinline__ uint32_t smem_u32(const void* p) {
    uint32_t a;
    asm("{ .reg .u64 t; cvta.to.shared.u64 t, %1; cvt.u32.u64 %0, t; }" : "=r"(a) : "l"(p));
    return a;
}

// ---- mbarrier + bulk-copy primitives (sm_90 base PTX, no 'a' features) -------------
__device__ __forceinline__ void mbar_init(uint32_t mbar, uint32_t cnt) {
    asm volatile("mbarrier.init.shared.b64 [%0], %1;" :: "r"(mbar), "r"(cnt) : "memory");
}
__device__ __forceinline__ void mbar_expect(uint32_t mbar, uint32_t tx) {
    asm volatile("mbarrier.arrive.expect_tx.shared.b64 _, [%0], %1;"
                 :: "r"(mbar), "r"(tx) : "memory");
}
__device__ __forceinline__ void mbar_wait(uint32_t mbar, uint32_t parity) {
    asm volatile(
        "{\n\t.reg .pred P;\n\t"
        "W%=:\n\t"
        "mbarrier.try_wait.parity.shared.b64 P, [%0], %1;\n\t"
        "@!P bra W%=;\n\t"
        "}\n\t" :: "r"(mbar), "r"(parity) : "memory");
}
__device__ __forceinline__ void bulk_cp16k(uint32_t dst, const float* src, uint32_t mbar) {
    asm volatile(
        "cp.async.bulk.shared::cta.global.mbarrier::complete_tx::bytes [%0], [%1], 16384, [%2];"
        :: "r"(dst), "l"(src), "r"(mbar) : "memory");
}

// ======================= precompute (exact fp32, original layouts) ==================
__global__ void precompute_kernel(
    const float* __restrict__ W_i, const float* __restrict__ W_o,
    const float* __restrict__ W_u, const float* __restrict__ W_f,
    const float* __restrict__ U_i, const float* __restrict__ U_o,
    const float* __restrict__ U_u, const float* __restrict__ U_f,
    const float* __restrict__ b_i, const float* __restrict__ b_o,
    const float* __restrict__ b_u, const float* __restrict__ b_f,
    const float* __restrict__ op_emb, const float* __restrict__ h_init)
{
    int t = blockIdx.x * blockDim.x + threadIdx.x;
    if (t < 4 * 4 * HID) {
        int k = t >> 12; int rem = t & 4095; int g = rem >> 10; int hh = rem & 1023;
        const float* W = (g == 0) ? W_i : (g == 1) ? W_o : (g == 2) ? W_u : W_f;
        const float* b = (g == 0) ? b_i : (g == 1) ? b_o : (g == 2) ? b_u : b_f;
        const float* x = op_emb + k * KD;
        const float* w = W + (size_t)hh * KD;
        float acc = b[hh];
        for (int kk = 0; kk < KD; kk++) acc += x[kk] * w[kk];
        g_opg[t] = acc;
    } else if (t < 4 * 4 * HID + 3 * HID) {
        int t2 = t - 4 * 4 * HID; int g = t2 >> 10; int hh = t2 & 1023;
        const float* U = (g == 0) ? U_i : (g == 1) ? U_o : U_u;
        const float* b = (g == 0) ? b_i : (g == 1) ? b_o : b_u;
        const float* u = U + (size_t)hh * KD;
        float acc = b[hh];
        for (int kk = 0; kk < KD; kk++) acc += (h_init[kk] + h_init[KD + kk]) * u[kk];
        g_lc3[t2] = acc;
    } else if (t < 4 * 4 * HID + 3 * HID + 2 * HID) {
        int t2 = t - (4 * 4 * HID + 3 * HID); int ci = t2 >> 10; int hh = t2 & 1023;
        const float* u = U_f + (size_t)hh * KD;
        float acc = b_f[hh];
        for (int kk = 0; kk < KD; kk++) acc += h_init[ci * KD + kk] * u[kk];
        g_lf[t2] = acc;
    }
}

// ===== convert operands: tf32-round into chunk-tiled swizzled layouts ===============
__global__ void conv_tf32_kernel(
    const float* __restrict__ W_i, const float* __restrict__ W_o,
    const float* __restrict__ W_u, const float* __restrict__ W_f,
    const float* __restrict__ U_i, const float* __restrict__ U_o,
    const float* __restrict__ U_u, const float* __restrict__ U_f,
    const float* __restrict__ tokens, const int* __restrict__ leaf_ids)
{
    const int SEG = (HID * KD) / 4;                       // 262144 float4
    int idx = blockIdx.x * blockDim.x + threadIdx.x;      // < 16*SEG
    const float4* src;
    float* dstbase;
    int drow, k;
    if (idx < 4 * SEG) {                                  // Wcat -> row 4*hh+g
        int s = idx / SEG; size_t i = (size_t)(idx % SEG) * 4;
        src = (const float4*)(((s == 0) ? W_i : (s == 1) ? W_o : (s == 2) ? W_u : W_f) + i);
        dstbase = g_wcat; drow = 4 * (int)(i >> 10) + s; k = (int)(i & 1023);
    } else if (idx < 7 * SEG) {                           // U3 -> row s*1024+hh
        int s = (idx - 4 * SEG) / SEG; size_t i = (size_t)((idx - 4 * SEG) % SEG) * 4;
        src = (const float4*)(((s == 0) ? U_i : (s == 1) ? U_o : U_u) + i);
        dstbase = g_ucat3; drow = s * HID + (int)(i >> 10); k = (int)(i & 1023);
    } else if (idx < 8 * SEG) {                           // Uf
        size_t i = (size_t)(idx - 7 * SEG) * 4;
        src = (const float4*)(U_f + i);
        dstbase = g_uf; drow = (int)(i >> 10); k = (int)(i & 1023);
    } else {                                              // tokens, gathered by leaf
        size_t i = (size_t)(idx - 8 * SEG) * 4;
        drow = (int)(i >> 10); k = (int)(i & 1023);
        src = (const float4*)(tokens + (size_t)leaf_ids[drow] * KD + k);
        dstbase = g_tok;
    }
    float4 v = *src;
    dstbase[tiled_off(drow, k + 0)] = f2tf_f(v.x);
    dstbase[tiled_off(drow, k + 1)] = f2tf_f(v.y);
    dstbase[tiled_off(drow, k + 2)] = f2tf_f(v.z);
    dstbase[tiled_off(drow, k + 3)] = f2tf_f(v.w);
}

// ======================= bulk-fed tf32 mma GEMM core, 128x128 tile ==================
// smem: 3 stages x (A 16KB | B 16KB) + 3 mbarriers. 512 thr, 16 warps of 32x32.
static constexpr int GEMM_SMEM_BYTES = 3 * 32768 + 64;    // 98368

__device__ __forceinline__ void mma_tf32(float* c, uint32_t a0, uint32_t a1,
                                         uint32_t a2, uint32_t a3,
                                         uint32_t b0, uint32_t b1) {
    asm volatile(
        "mma.sync.aligned.m16n8k8.row.col.f32.tf32.tf32.f32 "
        "{%0,%1,%2,%3}, {%4,%5,%6,%7}, {%8,%9}, {%0,%1,%2,%3};"
        : "+f"(c[0]), "+f"(c[1]), "+f"(c[2]), "+f"(c[3])
        : "r"(a0), "r"(a1), "r"(a2), "r"(a3), "r"(b0), "r"(b1));
}

// Atiles/Btiles point at this CTA's [row-block] base: 32 chunks x 4096 floats each.
__device__ __forceinline__ void gemm_mainloop(
    const float* __restrict__ Atiles, const float* __restrict__ Btiles,
    float acc[2][4][4])
{
    extern __shared__ __align__(16) uint32_t sm[];
    const uint32_t smb = smem_u32(sm);
    const int tid = threadIdx.x;

    if (tid == 0) {
        mbar_init(smb + 98304 + 0, 1);
        mbar_init(smb + 98304 + 8, 1);
        mbar_init(smb + 98304 + 16, 1);
    }
    __syncthreads();

    auto issue = [&](int it) {
        if (tid == 0) {
            const int s = it % 3;
            const uint32_t mb = smb + 98304 + s * 8;
            mbar_expect(mb, 32768u);
            bulk_cp16k(smb + s * 32768,         Atiles + (size_t)it * 4096, mb);
            bulk_cp16k(smb + s * 32768 + 16384, Btiles + (size_t)it * 4096, mb);
        }
    };

    const int wid  = tid >> 5;
    const int lane = tid & 31;
    const int wm  = (wid & 3) * 32;
    const int wn  = (wid >> 2) * 32;
    const int gid = lane >> 2;
    const int tig = lane & 3;
    const int sw  = (gid & 3) << 2;

    #pragma unroll
    for (int mi = 0; mi < 2; mi++)
        #pragma unroll
        for (int ni = 0; ni < 4; ni++)
            #pragma unroll
            for (int e = 0; e < 4; e++) acc[mi][ni][e] = 0.0f;

    auto compute = [&](int s) {
        const uint32_t* sa = sm + s * 8192;
        const uint32_t* sb = sa + 4096;
        #pragma unroll
        for (int kk = 0; kk < 32; kk += 8) {
            const int u2w = (((kk >> 1) + tig) ^ sw) << 1;
            uint2 a[2][2], b[4];
            #pragma unroll
            for (int mi = 0; mi < 2; mi++) {
                const uint32_t* ap = sa + (wm + mi * 16 + gid) * 32 + u2w;
                a[mi][0] = *(const uint2*)ap;
                a[mi][1] = *(const uint2*)(ap + 256);    // +8 rows
            }
            #pragma unroll
            for (int ni = 0; ni < 4; ni++)
                b[ni] = *(const uint2*)(sb + (wn + ni * 8 + gid) * 32 + u2w);
            #pragma unroll
            for (int mi = 0; mi < 2; mi++)
                #pragma unroll
                for (int ni = 0; ni < 4; ni++)
                    mma_tf32(acc[mi][ni],
                             a[mi][0].x, a[mi][1].x, a[mi][0].y, a[mi][1].y,
                             b[ni].x, b[ni].y);
        }
    };

    issue(0);
    issue(1);
    #pragma unroll 1
    for (int it = 0; it < 32; it++) {
        const int s = it % 3;
        mbar_wait(smb + 98304 + s * 8, (uint32_t)((it / 3) & 1));
        __syncthreads();                  // all consumed stage (it-1)%3; safe to refill
        if (it + 2 < 32) issue(it + 2);
        compute(s);
    }
}

// ---- leaf GEMM with fused gate epilogue (Wcat cols n = 4*hh+g) ---------------------
__global__ void __launch_bounds__(512, 1)
leaf_gemm_fused(const float* __restrict__ c_init,
                float* __restrict__ c_out, float* __restrict__ h_out,
                float* __restrict__ hs_out,
                const float* __restrict__ Atok, const float* __restrict__ Bw)
{
    const int m0 = blockIdx.y * 128;
    const int n0 = blockIdx.x * 128;
    float acc[2][4][4];
    gemm_mainloop(Atok + (size_t)(m0 >> 7) * 131072,
                  Bw   + (size_t)(n0 >> 7) * 131072, acc);

    const int wid  = threadIdx.x >> 5;
    const int lane = threadIdx.x & 31;
    const int wm  = (wid & 3) * 32;
    const int wn  = (wid >> 2) * 32;
    const int gid = lane >> 2;
    const int tig = lane & 3;
    const int pbit = tig & 1;           // 0: holds (i,o) preacts; 1: holds (u,f)

    #pragma unroll
    for (int ni = 0; ni < 4; ni++) {
        const int hh = ((n0 + wn) >> 2) + ni * 2 + (tig >> 1);
        const float lci = g_lc3[hh], lco = g_lc3[HID + hh], lcu = g_lc3[2 * HID + hh];
        const float lf0 = g_lf[hh],  lf1 = g_lf[HID + hh];
        const float ci0 = c_init[hh], ci1 = c_init[HID + hh];
        #pragma unroll
        for (int mi = 0; mi < 2; mi++) {
            #pragma unroll
            for (int half = 0; half < 2; half++) {
                const int r = m0 + wm + mi * 16 + gid + half * 8;
                const float x0 = acc[mi][ni][half * 2 + 0];
                const float x1 = acc[mi][ni][half * 2 + 1];
                const float p0 = __shfl_xor_sync(0xFFFFFFFFu, x0, 1);
                const float p1 = __shfl_xor_sync(0xFFFFFFFFu, x1, 1);
                const float gi = sigf(x0 + lci);
                const float go = sigf(x1 + lco);
                const float gu = tanhf(p0 + lcu);
                const float xf = p1;
                const float c = gi * gu + sigf(xf + lf0) * ci0 + sigf(xf + lf1) * ci1;
                const float h = go * tanhf(c);
                const float hsib = __shfl_xor_sync(0xFFFFFFFFu, h, 4);  // sibling leaf
                if (pbit == 0) {
                    c_out[(size_t)r * HID + hh] = c;
                    h_out[tiled_off(r, hh)] = f2tf_f(h);
                    if ((gid & 1) == 0)
                        hs_out[tiled_off(r >> 1, hh)] = f2tf_f(h + hsib);
                }
            }
        }
    }
}

// ---- merged per-level GEMM: bx<24 -> G3 (hs@U3^T), bx>=24 -> Gf (h@Uf^T) -----------
__global__ void __launch_bounds__(512, 1)
level_gemm(const float* __restrict__ hs, const float* __restrict__ h,
           const float* __restrict__ U3, const float* __restrict__ Uf,
           float* __restrict__ g3, float* __restrict__ gf, int m)
{
    const int bx = blockIdx.x;
    const int m0 = blockIdx.y * 128;
    const float* A;
    const float* B;
    float* C;
    int M, N, n0;
    if (bx < 24) {
        if (m0 >= m) return;
        A = hs; B = U3; C = g3; M = m; N = 3 * HID; n0 = bx * 128;
    } else {
        if (m0 >= 2 * m) return;
        A = h; B = Uf; C = gf; M = 2 * m; N = HID; n0 = (bx - 24) * 128;
    }
    float acc[2][4][4];
    gemm_mainloop(A + (size_t)(m0 >> 7) * 131072,
                  B + (size_t)(n0 >> 7) * 131072, acc);

    const int wid  = threadIdx.x >> 5;
    const int lane = threadIdx.x & 31;
    const int wm  = (wid & 3) * 32;
    const int wn  = (wid >> 2) * 32;
    const int gid = lane >> 2;
    const int tig = lane & 3;
    #pragma unroll
    for (int mi = 0; mi < 2; mi++) {
        const int r0 = m0 + wm + mi * 16 + gid;
        #pragma unroll
        for (int ni = 0; ni < 4; ni++) {
            const int col = n0 + wn + ni * 8 + tig * 2;
            if (r0 < M)
                *(float2*)(C + (size_t)r0 * N + col) = make_float2(acc[mi][ni][0], acc[mi][ni][1]);
            if (r0 + 8 < M)
                *(float2*)(C + (size_t)(r0 + 8) * N + col) = make_float2(acc[mi][ni][2], acc[mi][ni][3]);
        }
    }
}

// ========== node gate epilogues (pair-fused; h & hs tf32-rounded, tiled) ============
__global__ void node_gate_pair_kernel(int m, int off, const int* __restrict__ op_ids,
                                      const float* __restrict__ c_in,
                                      float* __restrict__ c_out, float* __restrict__ h_out,
                                      float* __restrict__ hs_out)
{
    int idx = blockIdx.x * blockDim.x + threadIdx.x;
    if (idx >= (m >> 1) * HID) return;
    int hh = idx & 1023;
    int p = idx >> 10;
    float hsum = 0.0f;
    #pragma unroll
    for (int s = 0; s < 2; s++) {
        const int j = 2 * p + s;
        const float* og = g_opg + op_ids[off + j] * 4 * HID;
        const float* g3 = g_g3 + (size_t)j * 3 * HID;
        float i = sigf(og[hh]            + g3[hh]);
        float o = sigf(og[HID + hh]      + g3[HID + hh]);
        float u = tanhf(og[2 * HID + hh] + g3[2 * HID + hh]);
        float xf = og[3 * HID + hh];
        float f0 = sigf(xf + g_gf[(size_t)(2 * j) * HID + hh]);
        float f1 = sigf(xf + g_gf[(size_t)(2 * j + 1) * HID + hh]);
        float c = i * u + f0 * c_in[(size_t)(2 * j) * HID + hh]
                        + f1 * c_in[(size_t)(2 * j + 1) * HID + hh];
        float h = o * tanhf(c);
        c_out[(size_t)j * HID + hh] = c;
        h_out[tiled_off(j, hh)] = f2tf_f(h);
        hsum += h;
    }
    hs_out[tiled_off(p, hh)] = f2tf_f(hsum);
}

__global__ void node_gate_root_kernel(const int* __restrict__ op_ids,
                                      const float* __restrict__ c_in,
                                      float* __restrict__ c_out, float* __restrict__ h_out)
{
    int hh = blockIdx.x * blockDim.x + threadIdx.x;
    if (hh >= HID) return;
    const float* og = g_opg + op_ids[0] * 4 * HID;
    float i = sigf(og[hh]            + g_g3[hh]);
    float o = sigf(og[HID + hh]      + g_g3[HID + hh]);
    float u = tanhf(og[2 * HID + hh] + g_g3[2 * HID + hh]);
    float xf = og[3 * HID + hh];
    float f0 = sigf(xf + g_gf[hh]);
    float f1 = sigf(xf + g_gf[HID + hh]);
    float c = i * u + f0 * c_in[hh] + f1 * c_in[HID + hh];
    c_out[hh] = c;
    h_out[hh] = o * tanhf(c);
}

// ======================= host launch ================================================
extern "C" void kernel_launch(void* const* d_in, const int* in_sizes, int n_in,
                              void* d_out, int out_size)
{
    const float* tokens   = (const float*)d_in[0];
    const int*   leaf_ids = (const int*)  d_in[1];
    const int*   op_ids   = (const int*)  d_in[2];
    const float* W_i = (const float*)d_in[3];
    const float* W_o = (const float*)d_in[4];
    const float* W_u = (const float*)d_in[5];
    const float* W_f = (const float*)d_in[6];
    const float* U_i = (const float*)d_in[7];
    const float* U_o = (const float*)d_in[8];
    const float* U_u = (const float*)d_in[9];
    const float* U_f = (const float*)d_in[10];
    const float* b_i = (const float*)d_in[11];
    const float* b_o = (const float*)d_in[12];
    const float* b_u = (const float*)d_in[13];
    const float* b_f = (const float*)d_in[14];
    const float* op_emb = (const float*)d_in[15];
    const float* c_init = (const float*)d_in[16];
    const float* h_init = (const float*)d_in[17];
    float* out = (float*)d_out;

    cudaFuncSetAttribute(leaf_gemm_fused, cudaFuncAttributeMaxDynamicSharedMemorySize, GEMM_SMEM_BYTES);
    cudaFuncSetAttribute(level_gemm,      cudaFuncAttributeMaxDynamicSharedMemorySize, GEMM_SMEM_BYTES);

    void* p;
    cudaGetSymbolAddress(&p, g_h);     float* hbase = (float*)p;
    cudaGetSymbolAddress(&p, g_c);     float* cbase = (float*)p;
    cudaGetSymbolAddress(&p, g_hs);    float* hsp   = (float*)p;
    cudaGetSymbolAddress(&p, g_g3);    float* g3p   = (float*)p;
    cudaGetSymbolAddress(&p, g_gf);    float* gfp   = (float*)p;
    cudaGetSymbolAddress(&p, g_wcat);  float* wcat  = (float*)p;
    cudaGetSymbolAddress(&p, g_ucat3); float* ucat3 = (float*)p;
    cudaGetSymbolAddress(&p, g_uf);    float* ufp   = (float*)p;
    cudaGetSymbolAddress(&p, g_tok);   float* tokp  = (float*)p;

    float* hbuf[2] = { hbase, hbase + (size_t)NLEAF * HID };
    float* cbuf[2] = { cbase, cbase + (size_t)NLEAF * HID };

    conv_tf32_kernel<<<(16 * (HID * KD / 4)) / 256, 256>>>(
        W_i, W_o, W_u, W_f, U_i, U_o, U_u, U_f, tokens, leaf_ids);
    precompute_kernel<<<84, 256>>>(W_i, W_o, W_u, W_f, U_i, U_o, U_u, U_f,
                                   b_i, b_o, b_u, b_f, op_emb, h_init);

    // Leaf level: GEMM + gates fused (M=8192, N=4096 gate-interleaved)
    leaf_gemm_fused<<<dim3(32, 64), 512, GEMM_SMEM_BYTES>>>(
        c_init, cbuf[0], hbuf[0], hsp, tokp, wcat);

    int cur = 0;
    for (int l = DEPTH - 1; l >= 0; l--) {
        const int m = 1 << l;
        const int off = m - 1;
        const int nxt = cur ^ 1;
        level_gemm<<<dim3(32, (2 * m + 127) / 128), 512, GEMM_SMEM_BYTES>>>(
            hsp, hbuf[cur], ucat3, ufp, g3p, gfp, m);
        if (m > 1) {
            node_gate_pair_kernel<<<((m / 2) * HID + 255) / 256, 256>>>(
                m, off, op_ids, cbuf[cur], cbuf[nxt], hbuf[nxt], hsp);
        } else {
            node_gate_root_kernel<<<4, 256>>>(op_ids, cbuf[cur], cbuf[nxt], hbuf[nxt]);
        }
        cur = nxt;
    }

    cudaMemcpyAsync(out,       cbuf[cur], HID * sizeof(float), cudaMemcpyDeviceToDevice, 0);
    cudaMemcpyAsync(out + HID, hbuf[cur], HID * sizeof(float), cudaMemcpyDeviceToDevice, 0);
}

// round 16
// speedup vs baseline: 1.8487x; 1.1082x over previous
#include <cuda_runtime.h>
#include <cstdint>
#include <math.h>

#define HID 1024
#define KD  1024
#define NLEAF 8192
#define DEPTH 13

// k-permutation within each 8-float group: [k0,k4,k1,k5,k2,k6,k3,k7]
#define KPERM(k) (((k) & ~7) | (((k) & 3) << 1) | (((k) >> 2) & 1))

// Chunk-tiled GEMM operand layout: [r>>7][k>>5][r&127][32 floats], k-permuted and
// XOR-swizzled (u2 index ^ ((r&3)<<2)) so a linear 16KB bulk copy into smem yields
// conflict-free LDS.64 fragment loads.
__device__ __forceinline__ size_t tiled_off(int r, int k) {
    const int w = KPERM(k) & 31;
    const int physw = ((((w >> 1) ^ ((r & 3) << 2)) & 15) << 1) | (w & 1);
    return ((size_t)(r >> 7) * 32 + (k >> 5)) * 4096 + (size_t)((r & 127) * 32 + physw);
}

// ======================= device scratch =============================================
__device__ float g_h[2][NLEAF * HID];          // tiled layout (rows = nodes)
__device__ float g_c[2][NLEAF * HID];          // natural layout
__device__ float g_hs[(NLEAF / 2) * HID];      // tiled layout (rows = pairs)
__device__ float g_g3[(NLEAF / 2) * 3 * HID];  // natural
__device__ float g_gf[NLEAF * HID];            // natural
__device__ float g_wcat[4 * HID * KD];         // tiled, gate-interleaved rows 4*hh+g
__device__ float g_ucat3[3 * HID * KD];        // tiled
__device__ float g_uf[HID * KD];               // tiled
__device__ float g_tok[NLEAF * KD];            // tiled, PRE-GATHERED by leaf_ids
__device__ float g_opg[4 * 4 * HID];
__device__ float g_lc3[3 * HID];
__device__ float g_lf[2 * HID];

__device__ __forceinline__ float sigf(float x) { return 1.0f / (1.0f + expf(-x)); }

__device__ __forceinline__ uint32_t f2tf(float x) {
    uint32_t r;
    asm("cvt.rna.tf32.f32 %0, %1;" : "=r"(r) : "f"(x));
    return r;
}
__device__ __forceinline__ float f2tf_f(float x) { return __uint_as_float(f2tf(x)); }
__device__ __forceinline__ uint32_t smem_u32(const void* p) {
    uint32_t a;
    asm("{ .reg .u64 t; cvta.to.shared.u64 t, %1; cvt.u32.u64 %0, t; }" : "=r"(a) : "l"(p));
    return a;
}

// ---- mbarrier + bulk-copy primitives (sm_90 base PTX, no 'a' features) -------------
__device__ __forceinline__ void mbar_init(uint32_t mbar, uint32_t cnt) {
    asm volatile("mbarrier.init.shared.b64 [%0], %1;" :: "r"(mbar), "r"(cnt) : "memory");
}
__device__ __forceinline__ void mbar_expect(uint32_t mbar, uint32_t tx) {
    asm volatile("mbarrier.arrive.expect_tx.shared.b64 _, [%0], %1;"
                 :: "r"(mbar), "r"(tx) : "memory");
}
__device__ __forceinline__ void mbar_wait(uint32_t mbar, uint32_t parity) {
    asm volatile(
        "{\n\t.reg .pred P;\n\t"
        "W%=:\n\t"
        "mbarrier.try_wait.parity.shared.b64 P, [%0], %1;\n\t"
        "@!P bra W%=;\n\t"
        "}\n\t" :: "r"(mbar), "r"(parity) : "memory");
}
__device__ __forceinline__ void bulk_cp16k(uint32_t dst, const float* src, uint32_t mbar) {
    asm volatile(
        "cp.async.bulk.shared::cta.global.mbarrier::complete_tx::bytes [%0], [%1], 16384, [%2];"
        :: "r"(dst), "l"(src), "r"(mbar) : "memory");
}

// ======================= precompute (exact fp32, original layouts) ==================
__global__ void precompute_kernel(
    const float* __restrict__ W_i, const float* __restrict__ W_o,
    const float* __restrict__ W_u, const float* __restrict__ W_f,
    const float* __restrict__ U_i, const float* __restrict__ U_o,
    const float* __restrict__ U_u, const float* __restrict__ U_f,
    const float* __restrict__ b_i, const float* __restrict__ b_o,
    const float* __restrict__ b_u, const float* __restrict__ b_f,
    const float* __restrict__ op_emb, const float* __restrict__ h_init)
{
    int t = blockIdx.x * blockDim.x + threadIdx.x;
    if (t < 4 * 4 * HID) {
        int k = t >> 12; int rem = t & 4095; int g = rem >> 10; int hh = rem & 1023;
        const float* W = (g == 0) ? W_i : (g == 1) ? W_o : (g == 2) ? W_u : W_f;
        const float* b = (g == 0) ? b_i : (g == 1) ? b_o : (g == 2) ? b_u : b_f;
        const float* x = op_emb + k * KD;
        const float* w = W + (size_t)hh * KD;
        float acc = b[hh];
        for (int kk = 0; kk < KD; kk++) acc += x[kk] * w[kk];
        g_opg[t] = acc;
    } else if (t < 4 * 4 * HID + 3 * HID) {
        int t2 = t - 4 * 4 * HID; int g = t2 >> 10; int hh = t2 & 1023;
        const float* U = (g == 0) ? U_i : (g == 1) ? U_o : U_u;
        const float* b = (g == 0) ? b_i : (g == 1) ? b_o : b_u;
        const float* u = U + (size_t)hh * KD;
        float acc = b[hh];
        for (int kk = 0; kk < KD; kk++) acc += (h_init[kk] + h_init[KD + kk]) * u[kk];
        g_lc3[t2] = acc;
    } else if (t < 4 * 4 * HID + 3 * HID + 2 * HID) {
        int t2 = t - (4 * 4 * HID + 3 * HID); int ci = t2 >> 10; int hh = t2 & 1023;
        const float* u = U_f + (size_t)hh * KD;
        float acc = b_f[hh];
        for (int kk = 0; kk < KD; kk++) acc += h_init[ci * KD + kk] * u[kk];
        g_lf[t2] = acc;
    }
}

// ===== convert operands: tf32-round into chunk-tiled swizzled layouts ===============
__global__ void conv_tf32_kernel(
    const float* __restrict__ W_i, const float* __restrict__ W_o,
    const float* __restrict__ W_u, const float* __restrict__ W_f,
    const float* __restrict__ U_i, const float* __restrict__ U_o,
    const float* __restrict__ U_u, const float* __restrict__ U_f,
    const float* __restrict__ tokens, const int* __restrict__ leaf_ids)
{
    const int SEG = (HID * KD) / 4;                       // 262144 float4
    int idx = blockIdx.x * blockDim.x + threadIdx.x;      // < 16*SEG
    const float4* src;
    float* dstbase;
    int drow, k;
    if (idx < 4 * SEG) {                                  // Wcat -> row 4*hh+g
        int s = idx / SEG; size_t i = (size_t)(idx % SEG) * 4;
        src = (const float4*)(((s == 0) ? W_i : (s == 1) ? W_o : (s == 2) ? W_u : W_f) + i);
        dstbase = g_wcat; drow = 4 * (int)(i >> 10) + s; k = (int)(i & 1023);
    } else if (idx < 7 * SEG) {                           // U3 -> row s*1024+hh
        int s = (idx - 4 * SEG) / SEG; size_t i = (size_t)((idx - 4 * SEG) % SEG) * 4;
        src = (const float4*)(((s == 0) ? U_i : (s == 1) ? U_o : U_u) + i);
        dstbase = g_ucat3; drow = s * HID + (int)(i >> 10); k = (int)(i & 1023);
    } else if (idx < 8 * SEG) {                           // Uf
        size_t i = (size_t)(idx - 7 * SEG) * 4;
        src = (const float4*)(U_f + i);
        dstbase = g_uf; drow = (int)(i >> 10); k = (int)(i & 1023);
    } else {                                              // tokens, gathered by leaf
        size_t i = (size_t)(idx - 8 * SEG) * 4;
        drow = (int)(i >> 10); k = (int)(i & 1023);
        src = (const float4*)(tokens + (size_t)leaf_ids[drow] * KD + k);
        dstbase = g_tok;
    }
    float4 v = *src;
    dstbase[tiled_off(drow, k + 0)] = f2tf_f(v.x);
    dstbase[tiled_off(drow, k + 1)] = f2tf_f(v.y);
    dstbase[tiled_off(drow, k + 2)] = f2tf_f(v.z);
    dstbase[tiled_off(drow, k + 3)] = f2tf_f(v.w);
}

// ======================= bulk-fed tf32 mma GEMM core, 128x128 tile ==================
// 256 threads, 8 warps (4M x 2N) of 32x64 warptiles; 3-stage bulk pipeline.
// smem per CTA: 3 x 32KB stages + mbarriers = 98368 B -> exactly 2 CTAs/SM.
static constexpr int GEMM_SMEM_BYTES = 3 * 32768 + 64;    // 98368

__device__ __forceinline__ void mma_tf32(float* c, uint32_t a0, uint32_t a1,
                                         uint32_t a2, uint32_t a3,
                                         uint32_t b0, uint32_t b1) {
    asm volatile(
        "mma.sync.aligned.m16n8k8.row.col.f32.tf32.tf32.f32 "
        "{%0,%1,%2,%3}, {%4,%5,%6,%7}, {%8,%9}, {%0,%1,%2,%3};"
        : "+f"(c[0]), "+f"(c[1]), "+f"(c[2]), "+f"(c[3])
        : "r"(a0), "r"(a1), "r"(a2), "r"(a3), "r"(b0), "r"(b1));
}

// Atiles/Btiles point at this CTA's [row-block] base: 32 chunks x 4096 floats each.
__device__ __forceinline__ void gemm_mainloop(
    const float* __restrict__ Atiles, const float* __restrict__ Btiles,
    float acc[2][8][4])
{
    extern __shared__ __align__(16) uint32_t sm[];
    const uint32_t smb = smem_u32(sm);
    const int tid = threadIdx.x;

    if (tid == 0) {
        mbar_init(smb + 98304 + 0, 1);
        mbar_init(smb + 98304 + 8, 1);
        mbar_init(smb + 98304 + 16, 1);
    }
    __syncthreads();

    auto issue = [&](int it) {
        if (tid == 0) {
            const int s = it % 3;
            const uint32_t mb = smb + 98304 + s * 8;
            mbar_expect(mb, 32768u);
            bulk_cp16k(smb + s * 32768,         Atiles + (size_t)it * 4096, mb);
            bulk_cp16k(smb + s * 32768 + 16384, Btiles + (size_t)it * 4096, mb);
        }
    };

    const int wid  = tid >> 5;
    const int lane = tid & 31;
    const int wm  = (wid & 3) * 32;
    const int wn  = (wid >> 2) * 64;
    const int gid = lane >> 2;
    const int tig = lane & 3;
    const int sw  = (gid & 3) << 2;

    #pragma unroll
    for (int mi = 0; mi < 2; mi++)
        #pragma unroll
        for (int ni = 0; ni < 8; ni++)
            #pragma unroll
            for (int e = 0; e < 4; e++) acc[mi][ni][e] = 0.0f;

    auto compute = [&](int s) {
        const uint32_t* sa = sm + s * 8192;
        const uint32_t* sb = sa + 4096;
        #pragma unroll
        for (int kk = 0; kk < 32; kk += 8) {
            const int u2w = (((kk >> 1) + tig) ^ sw) << 1;
            uint2 a[2][2], b[8];
            #pragma unroll
            for (int mi = 0; mi < 2; mi++) {
                const uint32_t* ap = sa + (wm + mi * 16 + gid) * 32 + u2w;
                a[mi][0] = *(const uint2*)ap;
                a[mi][1] = *(const uint2*)(ap + 256);    // +8 rows
            }
            #pragma unroll
            for (int ni = 0; ni < 8; ni++)
                b[ni] = *(const uint2*)(sb + (wn + ni * 8 + gid) * 32 + u2w);
            #pragma unroll
            for (int mi = 0; mi < 2; mi++)
                #pragma unroll
                for (int ni = 0; ni < 8; ni++)
                    mma_tf32(acc[mi][ni],
                             a[mi][0].x, a[mi][1].x, a[mi][0].y, a[mi][1].y,
                             b[ni].x, b[ni].y);
        }
    };

    issue(0);
    issue(1);
    #pragma unroll 1
    for (int it = 0; it < 32; it++) {
        const int s = it % 3;
        mbar_wait(smb + 98304 + s * 8, (uint32_t)((it / 3) & 1));
        __syncthreads();                  // all consumed stage (it-1)%3; safe to refill
        if (it + 2 < 32) issue(it + 2);
        compute(s);
    }
}

// ---- leaf GEMM with fused gate epilogue (Wcat cols n = 4*hh+g) ---------------------
__global__ void __launch_bounds__(256, 2)
leaf_gemm_fused(const float* __restrict__ c_init,
                float* __restrict__ c_out, float* __restrict__ h_out,
                float* __restrict__ hs_out,
                const float* __restrict__ Atok, const float* __restrict__ Bw)
{
    const int m0 = blockIdx.y * 128;
    const int n0 = blockIdx.x * 128;
    float acc[2][8][4];
    gemm_mainloop(Atok + (size_t)(m0 >> 7) * 131072,
                  Bw   + (size_t)(n0 >> 7) * 131072, acc);

    const int wid  = threadIdx.x >> 5;
    const int lane = threadIdx.x & 31;
    const int wm  = (wid & 3) * 32;
    const int wn  = (wid >> 2) * 64;
    const int gid = lane >> 2;
    const int tig = lane & 3;
    const int pbit = tig & 1;           // 0: holds (i,o) preacts; 1: holds (u,f)

    #pragma unroll
    for (int ni = 0; ni < 8; ni++) {
        const int hh = ((n0 + wn) >> 2) + ni * 2 + (tig >> 1);
        const float lci = g_lc3[hh], lco = g_lc3[HID + hh], lcu = g_lc3[2 * HID + hh];
        const float lf0 = g_lf[hh],  lf1 = g_lf[HID + hh];
        const float ci0 = c_init[hh], ci1 = c_init[HID + hh];
        #pragma unroll
        for (int mi = 0; mi < 2; mi++) {
            #pragma unroll
            for (int half = 0; half < 2; half++) {
                const int r = m0 + wm + mi * 16 + gid + half * 8;
                const float x0 = acc[mi][ni][half * 2 + 0];
                const float x1 = acc[mi][ni][half * 2 + 1];
                const float p0 = __shfl_xor_sync(0xFFFFFFFFu, x0, 1);
                const float p1 = __shfl_xor_sync(0xFFFFFFFFu, x1, 1);
                const float gi = sigf(x0 + lci);
                const float go = sigf(x1 + lco);
                const float gu = tanhf(p0 + lcu);
                const float xf = p1;
                const float c = gi * gu + sigf(xf + lf0) * ci0 + sigf(xf + lf1) * ci1;
                const float h = go * tanhf(c);
                const float hsib = __shfl_xor_sync(0xFFFFFFFFu, h, 4);  // sibling leaf
                if (pbit == 0) {
                    c_out[(size_t)r * HID + hh] = c;
                    h_out[tiled_off(r, hh)] = f2tf_f(h);
                    if ((gid & 1) == 0)
                        hs_out[tiled_off(r >> 1, hh)] = f2tf_f(h + hsib);
                }
            }
        }
    }
}

// ---- merged per-level GEMM: bx<24 -> G3 (hs@U3^T), bx>=24 -> Gf (h@Uf^T) -----------
__global__ void __launch_bounds__(256, 2)
level_gemm(const float* __restrict__ hs, const float* __restrict__ h,
           const float* __restrict__ U3, const float* __restrict__ Uf,
           float* __restrict__ g3, float* __restrict__ gf, int m)
{
    const int bx = blockIdx.x;
    const int m0 = blockIdx.y * 128;
    const float* A;
    const float* B;
    float* C;
    int M, N, n0;
    if (bx < 24) {
        if (m0 >= m) return;
        A = hs; B = U3; C = g3; M = m; N = 3 * HID; n0 = bx * 128;
    } else {
        if (m0 >= 2 * m) return;
        A = h; B = Uf; C = gf; M = 2 * m; N = HID; n0 = (bx - 24) * 128;
    }
    float acc[2][8][4];
    gemm_mainloop(A + (size_t)(m0 >> 7) * 131072,
                  B + (size_t)(n0 >> 7) * 131072, acc);

    const int wid  = threadIdx.x >> 5;
    const int lane = threadIdx.x & 31;
    const int wm  = (wid & 3) * 32;
    const int wn  = (wid >> 2) * 64;
    const int gid = lane >> 2;
    const int tig = lane & 3;
    #pragma unroll
    for (int mi = 0; mi < 2; mi++) {
        const int r0 = m0 + wm + mi * 16 + gid;
        #pragma unroll
        for (int ni = 0; ni < 8; ni++) {
            const int col = n0 + wn + ni * 8 + tig * 2;
            if (r0 < M)
                *(float2*)(C + (size_t)r0 * N + col) = make_float2(acc[mi][ni][0], acc[mi][ni][1]);
            if (r0 + 8 < M)
                *(float2*)(C + (size_t)(r0 + 8) * N + col) = make_float2(acc[mi][ni][2], acc[mi][ni][3]);
        }
    }
}

// ========== node gate epilogues (pair-fused; h & hs tf32-rounded, tiled) ============
__global__ void node_gate_pair_kernel(int m, int off, const int* __restrict__ op_ids,
                                      const float* __restrict__ c_in,
                                      float* __restrict__ c_out, float* __restrict__ h_out,
                                      float* __restrict__ hs_out)
{
    int idx = blockIdx.x * blockDim.x + threadIdx.x;
    if (idx >= (m >> 1) * HID) return;
    int hh = idx & 1023;
    int p = idx >> 10;
    float hsum = 0.0f;
    #pragma unroll
    for (int s = 0; s < 2; s++) {
        const int j = 2 * p + s;
        const float* og = g_opg + op_ids[off + j] * 4 * HID;
        const float* g3 = g_g3 + (size_t)j * 3 * HID;
        float i = sigf(og[hh]            + g3[hh]);
        float o = sigf(og[HID + hh]      + g3[HID + hh]);
        float u = tanhf(og[2 * HID + hh] + g3[2 * HID + hh]);
        float xf = og[3 * HID + hh];
        float f0 = sigf(xf + g_gf[(size_t)(2 * j) * HID + hh]);
        float f1 = sigf(xf + g_gf[(size_t)(2 * j + 1) * HID + hh]);
        float c = i * u + f0 * c_in[(size_t)(2 * j) * HID + hh]
                        + f1 * c_in[(size_t)(2 * j + 1) * HID + hh];
        float h = o * tanhf(c);
        c_out[(size_t)j * HID + hh] = c;
        h_out[tiled_off(j, hh)] = f2tf_f(h);
        hsum += h;
    }
    hs_out[tiled_off(p, hh)] = f2tf_f(hsum);
}

__global__ void node_gate_root_kernel(const int* __restrict__ op_ids,
                                      const float* __restrict__ c_in,
                                      float* __restrict__ c_out, float* __restrict__ h_out)
{
    int hh = blockIdx.x * blockDim.x + threadIdx.x;
    if (hh >= HID) return;
    const float* og = g_opg + op_ids[0] * 4 * HID;
    float i = sigf(og[hh]            + g_g3[hh]);
    float o = sigf(og[HID + hh]      + g_g3[HID + hh]);
    float u = tanhf(og[2 * HID + hh] + g_g3[2 * HID + hh]);
    float xf = og[3 * HID + hh];
    float f0 = sigf(xf + g_gf[hh]);
    float f1 = sigf(xf + g_gf[HID + hh]);
    float c = i * u + f0 * c_in[hh] + f1 * c_in[HID + hh];
    c_out[hh] = c;
    h_out[hh] = o * tanhf(c);
}

// ======================= host launch ================================================
extern "C" void kernel_launch(void* const* d_in, const int* in_sizes, int n_in,
                              void* d_out, int out_size)
{
    const float* tokens   = (const float*)d_in[0];
    const int*   leaf_ids = (const int*)  d_in[1];
    const int*   op_ids   = (const int*)  d_in[2];
    const float* W_i = (const float*)d_in[3];
    const float* W_o = (const float*)d_in[4];
    const float* W_u = (const float*)d_in[5];
    const float* W_f = (const float*)d_in[6];
    const float* U_i = (const float*)d_in[7];
    const float* U_o = (const float*)d_in[8];
    const float* U_u = (const float*)d_in[9];
    const float* U_f = (const float*)d_in[10];
    const float* b_i = (const float*)d_in[11];
    const float* b_o = (const float*)d_in[12];
    const float* b_u = (const float*)d_in[13];
    const float* b_f = (const float*)d_in[14];
    const float* op_emb = (const float*)d_in[15];
    const float* c_init = (const float*)d_in[16];
    const float* h_init = (const float*)d_in[17];
    float* out = (float*)d_out;

    cudaFuncSetAttribute(leaf_gemm_fused, cudaFuncAttributeMaxDynamicSharedMemorySize, GEMM_SMEM_BYTES);
    cudaFuncSetAttribute(level_gemm,      cudaFuncAttributeMaxDynamicSharedMemorySize, GEMM_SMEM_BYTES);

    void* p;
    cudaGetSymbolAddress(&p, g_h);     float* hbase = (float*)p;
    cudaGetSymbolAddress(&p, g_c);     float* cbase = (float*)p;
    cudaGetSymbolAddress(&p, g_hs);    float* hsp   = (float*)p;
    cudaGetSymbolAddress(&p, g_g3);    float* g3p   = (float*)p;
    cudaGetSymbolAddress(&p, g_gf);    float* gfp   = (float*)p;
    cudaGetSymbolAddress(&p, g_wcat);  float* wcat  = (float*)p;
    cudaGetSymbolAddress(&p, g_ucat3); float* ucat3 = (float*)p;
    cudaGetSymbolAddress(&p, g_uf);    float* ufp   = (float*)p;
    cudaGetSymbolAddress(&p, g_tok);   float* tokp  = (float*)p;

    float* hbuf[2] = { hbase, hbase + (size_t)NLEAF * HID };
    float* cbuf[2] = { cbase, cbase + (size_t)NLEAF * HID };

    conv_tf32_kernel<<<(16 * (HID * KD / 4)) / 256, 256>>>(
        W_i, W_o, W_u, W_f, U_i, U_o, U_u, U_f, tokens, leaf_ids);
    precompute_kernel<<<84, 256>>>(W_i, W_o, W_u, W_f, U_i, U_o, U_u, U_f,
                                   b_i, b_o, b_u, b_f, op_emb, h_init);

    // Leaf level: GEMM + gates fused (M=8192, N=4096 gate-interleaved)
    leaf_gemm_fused<<<dim3(32, 64), 256, GEMM_SMEM_BYTES>>>(
        c_init, cbuf[0], hbuf[0], hsp, tokp, wcat);

    int cur = 0;
    for (int l = DEPTH - 1; l >= 0; l--) {
        const int m = 1 << l;
        const int off = m - 1;
        const int nxt = cur ^ 1;
        level_gemm<<<dim3(32, (2 * m + 127) / 128), 256, GEMM_SMEM_BYTES>>>(
            hsp, hbuf[cur], ucat3, ufp, g3p, gfp, m);
        if (m > 1) {
            node_gate_pair_kernel<<<((m / 2) * HID + 255) / 256, 256>>>(
                m, off, op_ids, cbuf[cur], cbuf[nxt], hbuf[nxt], hsp);
        } else {
            node_gate_root_kernel<<<4, 256>>>(op_ids, cbuf[cur], cbuf[nxt], hbuf[nxt]);
        }
        cur = nxt;
    }

    cudaMemcpyAsync(out,       cbuf[cur], HID * sizeof(float), cudaMemcpyDeviceToDevice, 0);
    cudaMemcpyAsync(out + HID, hbuf[cur], HID * sizeof(float), cudaMemcpyDeviceToDevice, 0);
}